// round 1
// baseline (speedup 1.0000x reference)
#include <cuda_runtime.h>
#include <math.h>

// Problem constants (fixed by the reference)
#define NV 100000
#define NB 8

// Scratch: transposed, padded layouts. One vertex = NB float4 = 128 B line.
__device__ float4 g_xt[NV * NB];    // 12.8 MB
__device__ float4 g_dxt[NV * NB];   // 12.8 MB
__device__ double g_acc[NB];

// ---------------------------------------------------------------------------
// Kernel 1: transpose (B, NV, 3) -> (NV, B, float4) for x and dx.
// Thread = (v, b) with b fastest -> writes are fully coalesced 128B lines.
// Also zeroes the accumulators (stream-ordered before the gather kernel).
// ---------------------------------------------------------------------------
__global__ void transpose_kernel(const float* __restrict__ dx,
                                 const float* __restrict__ x) {
    int tid = blockIdx.x * blockDim.x + threadIdx.x;
    if (blockIdx.x == 0 && threadIdx.x < NB) g_acc[threadIdx.x] = 0.0;
    if (tid >= NV * NB) return;
    int b = tid & (NB - 1);
    int v = tid >> 3;
    size_t base = ((size_t)b * NV + v) * 3;
    g_xt[tid]  = make_float4(x[base + 0],  x[base + 1],  x[base + 2],  0.f);
    g_dxt[tid] = make_float4(dx[base + 0], dx[base + 1], dx[base + 2], 0.f);
}

// ---------------------------------------------------------------------------
// Kernel 2: edge gather + reduce.
// 8 lanes per edge (lane%8 = batch), 4 edges per warp, grid-stride over edges.
// Per edge: 4 x 128B fully-coalesced line reads from L2-resident scratch.
// ---------------------------------------------------------------------------
__global__ void __launch_bounds__(256)
edge_kernel(const int* __restrict__ es, const int* __restrict__ ed, int E) {
    const int lane = threadIdx.x & 31;
    const int b    = lane & 7;        // batch index
    const int grp  = lane >> 3;       // edge slot within warp (0..3)
    const int warp = threadIdx.x >> 5;
    const int warpsPerBlock = blockDim.x >> 5;
    const int gwarp  = blockIdx.x * warpsPerBlock + warp;
    const int nwarps = gridDim.x * warpsPerBlock;

    float acc = 0.f;
    for (int e = gwarp * 4 + grp; e < E; e += nwarps * 4) {
        int s = es[e];
        int d = ed[e];
        float4 xs = g_xt[s * NB + b];
        float4 xd = g_xt[d * NB + b];
        float4 ps = g_dxt[s * NB + b];
        float4 pd = g_dxt[d * NB + b];
        float ex = xd.x - xs.x, ey = xd.y - xs.y, ez = xd.z - xs.z;
        float fx = pd.x - ps.x, fy = pd.y - ps.y, fz = pd.z - ps.z;
        float diffx  = ex * ex + ey * ey + ez * ez;
        float diffdx = fx * fx + fy * fy + fz * fz;
        acc += fabsf(diffx - diffdx);
    }

    // Combine the 4 edge-groups within the warp: lanes end up holding the
    // per-batch partial sum (replicated across groups).
    acc += __shfl_xor_sync(0xffffffff, acc, 8);
    acc += __shfl_xor_sync(0xffffffff, acc, 16);

    __shared__ float sacc[8][9];   // [warp][batch], pad to dodge bank conflicts
    if (lane < 8) sacc[warp][b] = acc;
    __syncthreads();

    if (warp == 0 && lane < 8) {
        float s = 0.f;
        #pragma unroll
        for (int w = 0; w < 8; w++) s += (w < warpsPerBlock) ? sacc[w][lane] : 0.f;
        atomicAdd(&g_acc[lane], (double)s);
    }
}

// ---------------------------------------------------------------------------
// Kernel 3: finalize — divide by E, write output.
// ---------------------------------------------------------------------------
__global__ void finalize_kernel(float* __restrict__ out, int E) {
    if (threadIdx.x < NB)
        out[threadIdx.x] = (float)(g_acc[threadIdx.x] / (double)E);
}

extern "C" void kernel_launch(void* const* d_in, const int* in_sizes, int n_in,
                              void* d_out, int out_size) {
    // metadata order: dx, x, edge_src, edge_dst
    const float* dx = (const float*)d_in[0];
    const float* x  = (const float*)d_in[1];
    const int* es   = (const int*)d_in[2];
    const int* ed   = (const int*)d_in[3];
    float* out      = (float*)d_out;
    const int E     = in_sizes[2];

    {
        int threads = 256;
        int blocks = (NV * NB + threads - 1) / threads;
        transpose_kernel<<<blocks, threads>>>(dx, x);
    }
    {
        int threads = 256;
        int blocks = 148 * 8;   // grid-stride; keeps atomic count tiny
        edge_kernel<<<blocks, threads>>>(es, ed, E);
    }
    finalize_kernel<<<1, 32>>>(out, E);
}

// round 2
// speedup vs baseline: 1.0534x; 1.0534x over previous
#include <cuda_runtime.h>
#include <math.h>

// Problem constants (fixed by the reference)
#define NV 100000
#define NB 8
#define REC 6                 // floats per (vertex,batch) record: x0 x1 x2 dx0 dx1 dx2
#define TILE_V 128

// Combined scratch: g_v[((v*NB + b)*REC) + c]  -> 24B record per (v,b),
// one vertex = 192B contiguous. Total 19.2 MB (fully L2-resident).
__device__ float g_v[(size_t)NV * NB * REC];
__device__ double g_acc[NB];

// ---------------------------------------------------------------------------
// Kernel 1: tiled transpose (B, NV, 3) x2 arrays  ->  (NV, B, 6) records.
// Reads coalesced per-batch rows into smem, writes coalesced contiguous tile.
// Also zeroes the accumulators (stream-ordered before the edge kernel).
// ---------------------------------------------------------------------------
__global__ void __launch_bounds__(256)
transpose_kernel(const float* __restrict__ dx, const float* __restrict__ x) {
    __shared__ float sx[NB][TILE_V * 3 + 1];
    __shared__ float sdx[NB][TILE_V * 3 + 1];

    if (blockIdx.x == 0 && threadIdx.x < NB) g_acc[threadIdx.x] = 0.0;

    const int v0 = blockIdx.x * TILE_V;
    const int nv = min(TILE_V, NV - v0);
    const int nflt = nv * 3;

    // Read phase: for each batch b, a contiguous run of nv*3 floats. Coalesced.
    for (int i = threadIdx.x; i < NB * TILE_V * 3; i += blockDim.x) {
        int b = i / (TILE_V * 3);
        int j = i - b * (TILE_V * 3);
        float vx = 0.f, vdx = 0.f;
        if (j < nflt) {
            size_t g = (size_t)b * NV * 3 + (size_t)v0 * 3 + j;
            vx = x[g];
            vdx = dx[g];
        }
        sx[b][j] = vx;
        sdx[b][j] = vdx;
    }
    __syncthreads();

    // Write phase: tile output region is contiguous: g_v[v0*NB*REC ...]. Coalesced.
    float* outp = g_v + (size_t)v0 * NB * REC;
    const int nout = nv * NB * REC;
    for (int i = threadIdx.x; i < nout; i += blockDim.x) {
        int rec = i / REC;          // v*NB + b within tile
        int c = i - rec * REC;
        int v = rec >> 3;
        int b = rec & (NB - 1);
        float val = (c < 3) ? sx[b][v * 3 + c] : sdx[b][v * 3 + (c - 3)];
        outp[i] = val;
    }
}

// ---------------------------------------------------------------------------
// Kernel 2: edge gather + reduce.
// 8 lanes per edge (lane&7 = batch), 4 edges per warp, grid-stride.
// Symmetry: only edges with s < d are evaluated (each undirected edge appears
// in both directions in the input; self-loops contribute 0). Finalize doubles.
// Per evaluated edge: 2 endpoints x 24B x 8 batches = 384B of fully-used sectors.
// ---------------------------------------------------------------------------
__global__ void __launch_bounds__(256)
edge_kernel(const int* __restrict__ es, const int* __restrict__ ed, int E) {
    const int lane = threadIdx.x & 31;
    const int b    = lane & 7;
    const int grp  = lane >> 3;
    const int warp = threadIdx.x >> 5;
    const int warpsPerBlock = blockDim.x >> 5;
    const int gwarp  = blockIdx.x * warpsPerBlock + warp;
    const int nwarps = gridDim.x * warpsPerBlock;

    float acc = 0.f;
    #pragma unroll 4
    for (int e = gwarp * 4 + grp; e < E; e += nwarps * 4) {
        int s = es[e];
        int d = ed[e];
        if (s < d) {
            const float* ps = g_v + ((size_t)s * NB + b) * REC;
            const float* pd = g_v + ((size_t)d * NB + b) * REC;
            float2 s01 = *(const float2*)(ps);
            float2 s23 = *(const float2*)(ps + 2);
            float2 s45 = *(const float2*)(ps + 4);
            float2 d01 = *(const float2*)(pd);
            float2 d23 = *(const float2*)(pd + 2);
            float2 d45 = *(const float2*)(pd + 4);
            float ex = d01.x - s01.x, ey = d01.y - s01.y, ez = d23.x - s23.x;
            float fx = d23.y - s23.y, fy = d45.x - s45.x, fz = d45.y - s45.y;
            float diffx  = ex * ex + ey * ey + ez * ez;
            float diffdx = fx * fx + fy * fy + fz * fz;
            acc += fabsf(diffx - diffdx);
        }
    }

    // Fold the 4 edge-groups of the warp down to per-batch partials.
    acc += __shfl_xor_sync(0xffffffff, acc, 8);
    acc += __shfl_xor_sync(0xffffffff, acc, 16);

    __shared__ float sacc[8][9];
    if (lane < 8) sacc[warp][b] = acc;
    __syncthreads();

    if (warp == 0 && lane < 8) {
        float s = 0.f;
        #pragma unroll
        for (int w = 0; w < 8; w++) s += (w < warpsPerBlock) ? sacc[w][lane] : 0.f;
        atomicAdd(&g_acc[lane], (double)s);
    }
}

// ---------------------------------------------------------------------------
// Kernel 3: finalize — double (symmetry) and divide by E.
// ---------------------------------------------------------------------------
__global__ void finalize_kernel(float* __restrict__ out, int E) {
    if (threadIdx.x < NB)
        out[threadIdx.x] = (float)(2.0 * g_acc[threadIdx.x] / (double)E);
}

extern "C" void kernel_launch(void* const* d_in, const int* in_sizes, int n_in,
                              void* d_out, int out_size) {
    // metadata order: dx, x, edge_src, edge_dst
    const float* dx = (const float*)d_in[0];
    const float* x  = (const float*)d_in[1];
    const int* es   = (const int*)d_in[2];
    const int* ed   = (const int*)d_in[3];
    float* out      = (float*)d_out;
    const int E     = in_sizes[2];

    {
        int blocks = (NV + TILE_V - 1) / TILE_V;
        transpose_kernel<<<blocks, 256>>>(dx, x);
    }
    edge_kernel<<<148 * 8, 256>>>(es, ed, E);
    finalize_kernel<<<1, 32>>>(out, E);
}

// round 3
// speedup vs baseline: 1.1311x; 1.0738x over previous
#include <cuda_runtime.h>
#include <cuda_fp16.h>
#include <math.h>

// Problem constants (fixed by the reference)
#define NV 100000
#define NB 8
#define TILE_V 64
#define EMAX 1200064          // directed edges <= 6*NF = 1.2M; s<d half <= 600k

// Scratch: fp16 records. g_v[((v*NB+b)*3) + k] as uint (=half2):
//   k=0:(x0,x1) k=1:(x2,dx0) k=2:(dx1,dx2). 12B per (v,b), 96B per vertex. 9.6 MB.
__device__ unsigned int g_v[(size_t)NV * NB * 3];
__device__ int2 g_edges[EMAX / 2 + 64];
__device__ int g_ecount;
__device__ double g_acc[NB];

// ---------------------------------------------------------------------------
// Kernel 1: transpose (B, NV, 3) x2 -> (NV, B, 6-half) records. ALU-lean.
// ---------------------------------------------------------------------------
__global__ void __launch_bounds__(256)
transpose_kernel(const float* __restrict__ dx, const float* __restrict__ x) {
    __shared__ float sx[NB][TILE_V * 3 + 1];
    __shared__ float sdx[NB][TILE_V * 3 + 1];

    if (blockIdx.x == 0) {
        if (threadIdx.x < NB) g_acc[threadIdx.x] = 0.0;
        if (threadIdx.x == NB) g_ecount = 0;
    }

    const int tid = threadIdx.x;
    const int v0 = blockIdx.x * TILE_V;
    const int nv = min(TILE_V, NV - v0);
    const int nflt = nv * 3;

    // Read: per batch b, a contiguous run of nv*3 floats. 6 unrolled iters.
    #pragma unroll
    for (int k = 0; k < 6; k++) {
        int i = k * 256 + tid;                 // [0, 1536)
        int b = i / (TILE_V * 3);              // const-div -> mul/shift
        int j = i - b * (TILE_V * 3);
        float vx = 0.f, vdx = 0.f;
        if (j < nflt) {
            size_t g = (size_t)b * (NV * 3) + (size_t)v0 * 3 + j;
            vx = x[g];
            vdx = dx[g];
        }
        sx[b][j] = vx;
        sdx[b][j] = vdx;
    }
    __syncthreads();

    // Write: contiguous uint (half2) stream: 64*8 records * 3 uints = 1536.
    unsigned int* outp = g_v + (size_t)v0 * NB * 3;
    #pragma unroll
    for (int k = 0; k < 6; k++) {
        int o = k * 256 + tid;                 // [0, 1536)
        int rec = o / 3;                       // const-div
        int h = o - rec * 3;
        int v = rec >> 3;
        int b = rec & (NB - 1);
        if (v < nv) {
            int j = v * 3;
            float a, c;
            if (h == 0)      { a = sx[b][j];     c = sx[b][j + 1]; }
            else if (h == 1) { a = sx[b][j + 2]; c = sdx[b][j];    }
            else             { a = sdx[b][j + 1]; c = sdx[b][j + 2]; }
            __half2 hv = __floats2half2_rn(a, c);
            outp[o] = *(unsigned int*)&hv;
        }
    }
}

// ---------------------------------------------------------------------------
// Kernel 2: compact the s<d edges into g_edges (int2). Block-aggregated:
// one global atomic per block, warp-scan ranks. Order preserved per block.
// ---------------------------------------------------------------------------
__global__ void __launch_bounds__(256)
compact_kernel(const int* __restrict__ es, const int* __restrict__ ed, int E) {
    const int tid = threadIdx.x;
    const int lane = tid & 31, warp = tid >> 5;
    const int base = blockIdx.x * 2048;

    int s[8], d[8];
    bool f[8];
    int cnt = 0;
    #pragma unroll
    for (int k = 0; k < 8; k++) {
        int e = base + k * 256 + tid;
        bool fl = false; int ss = 0, dd = 0;
        if (e < E) { ss = es[e]; dd = ed[e]; fl = ss < dd; }
        s[k] = ss; d[k] = dd; f[k] = fl; cnt += fl;
    }

    // Block exclusive scan over per-thread counts.
    int inc = cnt;
    #pragma unroll
    for (int o = 1; o < 32; o <<= 1) {
        int t = __shfl_up_sync(0xffffffffu, inc, o);
        if (lane >= o) inc += t;
    }
    __shared__ int wsum[8];
    __shared__ int sbase;
    if (lane == 31) wsum[warp] = inc;
    __syncthreads();
    if (tid == 0) {
        int tot = 0;
        #pragma unroll
        for (int w = 0; w < 8; w++) { int t = wsum[w]; wsum[w] = tot; tot += t; }
        sbase = atomicAdd(&g_ecount, tot);
    }
    __syncthreads();

    int pos = sbase + wsum[warp] + (inc - cnt);
    #pragma unroll
    for (int k = 0; k < 8; k++)
        if (f[k]) g_edges[pos++] = make_int2(s[k], d[k]);
}

// ---------------------------------------------------------------------------
// Kernel 3: edge gather + reduce over compacted edges. No divergence.
// 8 lanes per edge (lane&7 = batch), 4 edges per warp, grid-stride.
// ---------------------------------------------------------------------------
__global__ void __launch_bounds__(256)
edge_kernel() {
    const int EC = g_ecount;
    const int lane = threadIdx.x & 31;
    const int b    = lane & 7;
    const int grp  = lane >> 3;
    const int warp = threadIdx.x >> 5;
    const int gwarp  = blockIdx.x * 8 + warp;
    const int nwarps = gridDim.x * 8;

    float acc = 0.f;
    #pragma unroll 2
    for (int e = gwarp * 4 + grp; e < EC; e += nwarps * 4) {
        int2 sd = g_edges[e];
        const unsigned int* ps = g_v + ((unsigned)sd.x * NB + b) * 3;
        const unsigned int* pd = g_v + ((unsigned)sd.y * NB + b) * 3;
        unsigned su0 = ps[0], su1 = ps[1], su2 = ps[2];
        unsigned du0 = pd[0], du1 = pd[1], du2 = pd[2];
        float2 sa = __half22float2(*(__half2*)&su0);
        float2 sb = __half22float2(*(__half2*)&su1);
        float2 sc = __half22float2(*(__half2*)&su2);
        float2 da = __half22float2(*(__half2*)&du0);
        float2 db = __half22float2(*(__half2*)&du1);
        float2 dc = __half22float2(*(__half2*)&du2);
        float ex = da.x - sa.x, ey = da.y - sa.y, ez = db.x - sb.x;
        float fx = db.y - sb.y, fy = dc.x - sc.x, fz = dc.y - sc.y;
        float diffx  = ex * ex + ey * ey + ez * ez;
        float diffdx = fx * fx + fy * fy + fz * fz;
        acc += fabsf(diffx - diffdx);
    }

    // Fold the 4 edge-groups of the warp down to per-batch partials.
    acc += __shfl_xor_sync(0xffffffff, acc, 8);
    acc += __shfl_xor_sync(0xffffffff, acc, 16);

    __shared__ float sacc[8][9];
    if (lane < 8) sacc[warp][b] = acc;
    __syncthreads();

    if (warp == 0 && lane < 8) {
        float s = 0.f;
        #pragma unroll
        for (int w = 0; w < 8; w++) s += sacc[w][lane];
        atomicAdd(&g_acc[lane], (double)s);
    }
}

// ---------------------------------------------------------------------------
// Kernel 4: finalize — double (symmetry) and divide by E (directed count).
// ---------------------------------------------------------------------------
__global__ void finalize_kernel(float* __restrict__ out, int E) {
    if (threadIdx.x < NB)
        out[threadIdx.x] = (float)(2.0 * g_acc[threadIdx.x] / (double)E);
}

extern "C" void kernel_launch(void* const* d_in, const int* in_sizes, int n_in,
                              void* d_out, int out_size) {
    // metadata order: dx, x, edge_src, edge_dst
    const float* dx = (const float*)d_in[0];
    const float* x  = (const float*)d_in[1];
    const int* es   = (const int*)d_in[2];
    const int* ed   = (const int*)d_in[3];
    float* out      = (float*)d_out;
    const int E     = in_sizes[2];

    transpose_kernel<<<(NV + TILE_V - 1) / TILE_V, 256>>>(dx, x);
    compact_kernel<<<(E + 2047) / 2048, 256>>>(es, ed, E);
    edge_kernel<<<148 * 8, 256>>>();
    finalize_kernel<<<1, 32>>>(out, E);
}

// round 4
// speedup vs baseline: 1.3019x; 1.1509x over previous
#include <cuda_runtime.h>
#include <cuda_fp16.h>
#include <math.h>

// Problem constants (fixed by the reference)
#define NV 100000
#define NB 8
#define TILE_V 64
#define NTILES ((NV + TILE_V - 1) / TILE_V)   // 1563
#define NBLK 592                               // 148 SMs x 4 blocks, all resident
#define CHUNK 2048
#define EMAX 1200064

// Scratch: 16B fp16 record per (v,b): half2{x0,x1}, half2{x2,dx0}, half2{dx1,dx2}, pad.
// One vertex = 8 records = 128B line. Total 12.8 MB (L2-resident).
__device__ uint4 g_v[(size_t)NV * NB];
__device__ int2 g_edges[EMAX / 2 + 128];
__device__ int g_ecount;                 // zero-init; re-zeroed at end of every launch
__device__ double g_acc[NB];             // zero-init; re-zeroed at end of every launch
__device__ volatile unsigned g_bar_gen;  // generation barrier: no per-launch reset needed
__device__ unsigned g_bar_cnt;

__device__ __forceinline__ void grid_barrier() {
    __syncthreads();
    if (threadIdx.x == 0) {
        unsigned gen = g_bar_gen;
        __threadfence();
        if (atomicAdd(&g_bar_cnt, 1u) == NBLK - 1) {
            g_bar_cnt = 0;
            __threadfence();
            g_bar_gen = gen + 1;
        } else {
            while (g_bar_gen == gen) __nanosleep(64);
            __threadfence();
        }
    }
    __syncthreads();
}

__global__ void __launch_bounds__(256, 4)
fused_kernel(const float* __restrict__ dx, const float* __restrict__ x,
             const int* __restrict__ es, const int* __restrict__ ed,
             float* __restrict__ out, int E) {
    __shared__ float sx[NB][TILE_V * 3 + 1];
    __shared__ float sdx[NB][TILE_V * 3 + 1];
    __shared__ int wsum[8];
    __shared__ int sbase;
    __shared__ float sacc[8][9];

    const int tid  = threadIdx.x;
    const int bid  = blockIdx.x;
    const int lane = tid & 31;
    const int warp = tid >> 5;

    // ------------------- phase 1a: transpose to fp16 records -------------------
    for (int t = bid; t < NTILES; t += NBLK) {
        const int v0 = t * TILE_V;
        const int nv = min(TILE_V, NV - v0);
        const int nflt = nv * 3;
        #pragma unroll
        for (int k = 0; k < 6; k++) {
            int i = k * 256 + tid;                 // [0, 1536)
            int b = i / (TILE_V * 3);
            int j = i - b * (TILE_V * 3);
            float vx = 0.f, vdx = 0.f;
            if (j < nflt) {
                size_t g = (size_t)b * (NV * 3) + (size_t)v0 * 3 + j;
                vx = x[g];
                vdx = dx[g];
            }
            sx[b][j] = vx;
            sdx[b][j] = vdx;
        }
        __syncthreads();
        uint4* outp = g_v + (size_t)v0 * NB;
        #pragma unroll
        for (int k = 0; k < 2; k++) {
            int rec = k * 256 + tid;               // [0, 512)
            int v = rec >> 3;
            int b = rec & (NB - 1);
            if (v < nv) {
                int j = v * 3;
                __half2 h0 = __floats2half2_rn(sx[b][j],      sx[b][j + 1]);
                __half2 h1 = __floats2half2_rn(sx[b][j + 2],  sdx[b][j]);
                __half2 h2 = __floats2half2_rn(sdx[b][j + 1], sdx[b][j + 2]);
                uint4 r;
                r.x = *(unsigned int*)&h0;
                r.y = *(unsigned int*)&h1;
                r.z = *(unsigned int*)&h2;
                r.w = 0u;
                outp[rec] = r;
            }
        }
        __syncthreads();
    }

    // ------------------- phase 1b: compact s<d edges -------------------
    const int nchunks = (E + CHUNK - 1) / CHUNK;
    for (int c = bid; c < nchunks; c += NBLK) {
        const int base = c * CHUNK;
        int s[8], d[8];
        bool f[8];
        int cnt = 0;
        #pragma unroll
        for (int k = 0; k < 8; k++) {
            int e = base + k * 256 + tid;
            bool fl = false; int ss = 0, dd = 0;
            if (e < E) { ss = es[e]; dd = ed[e]; fl = ss < dd; }
            s[k] = ss; d[k] = dd; f[k] = fl; cnt += fl;
        }
        int inc = cnt;
        #pragma unroll
        for (int o = 1; o < 32; o <<= 1) {
            int t2 = __shfl_up_sync(0xffffffffu, inc, o);
            if (lane >= o) inc += t2;
        }
        if (lane == 31) wsum[warp] = inc;
        __syncthreads();
        if (tid == 0) {
            int tot = 0;
            #pragma unroll
            for (int w = 0; w < 8; w++) { int t2 = wsum[w]; wsum[w] = tot; tot += t2; }
            sbase = atomicAdd(&g_ecount, tot);
        }
        __syncthreads();
        int pos = sbase + wsum[warp] + (inc - cnt);
        #pragma unroll
        for (int k = 0; k < 8; k++)
            if (f[k]) g_edges[pos++] = make_int2(s[k], d[k]);
        __syncthreads();
    }

    grid_barrier();

    // ------------------- phase 2: edge gather + reduce -------------------
    const int EC  = *(volatile int*)&g_ecount;
    const int b   = lane & 7;
    const int grp = lane >> 3;
    const int gwarp = bid * 8 + warp;

    float acc = 0.f;
    for (int e = gwarp * 4 + grp; e < EC; e += NBLK * 8 * 4) {
        int2 sd = g_edges[e];
        uint4 rs = g_v[(unsigned)sd.x * NB + b];
        uint4 rd = g_v[(unsigned)sd.y * NB + b];
        __half2 e0 = __hsub2(*(__half2*)&rd.x, *(__half2*)&rs.x);
        __half2 e1 = __hsub2(*(__half2*)&rd.y, *(__half2*)&rs.y);
        __half2 e2 = __hsub2(*(__half2*)&rd.z, *(__half2*)&rs.z);
        float2 f0 = __half22float2(e0);
        float2 f1 = __half22float2(e1);
        float2 f2 = __half22float2(e2);
        float diffx = f0.x * f0.x + f0.y * f0.y + f1.x * f1.x;
        float diffd = f1.y * f1.y + f2.x * f2.x + f2.y * f2.y;
        acc += fabsf(diffx - diffd);
    }

    acc += __shfl_xor_sync(0xffffffff, acc, 8);
    acc += __shfl_xor_sync(0xffffffff, acc, 16);

    if (lane < 8) sacc[warp][b] = acc;
    __syncthreads();
    if (warp == 0 && lane < 8) {
        float s = 0.f;
        #pragma unroll
        for (int w = 0; w < 8; w++) s += sacc[w][lane];
        atomicAdd(&g_acc[lane], (double)s);
    }

    grid_barrier();

    // ------------------- finalize + reset launch state -------------------
    if (bid == 0) {
        if (tid < NB) {
            out[tid] = (float)(2.0 * g_acc[tid] / (double)E);
            g_acc[tid] = 0.0;
        }
        if (tid == NB) g_ecount = 0;
    }
}

extern "C" void kernel_launch(void* const* d_in, const int* in_sizes, int n_in,
                              void* d_out, int out_size) {
    // metadata order: dx, x, edge_src, edge_dst
    const float* dx = (const float*)d_in[0];
    const float* x  = (const float*)d_in[1];
    const int* es   = (const int*)d_in[2];
    const int* ed   = (const int*)d_in[3];
    float* out      = (float*)d_out;
    const int E     = in_sizes[2];

    fused_kernel<<<NBLK, 256>>>(dx, x, es, ed, out, E);
}

// round 5
// speedup vs baseline: 1.3143x; 1.0095x over previous
#include <cuda_runtime.h>
#include <cuda_fp16.h>
#include <math.h>

// Problem constants (fixed by the reference)
#define NV 100000
#define NB 8
#define TILE_V 128
#define NTILES ((NV + TILE_V - 1) / TILE_V)   // 782
#define NBLK 592                               // 148 SMs x 4 blocks, all resident
#define TBLK 400                               // transpose blocks
#define CBLK (NBLK - TBLK)                     // compact blocks (192)
#define CHUNK 2048
#define EMAX 1200064

// Scratch: 16B fp16 record per (v,b): half2{x0,x1}, half2{x2,dx0}, half2{dx1,dx2}, pad.
// One vertex = 8 records = 128B line. Total 12.8 MB (L2-resident).
__device__ uint4 g_v[(size_t)NV * NB];
__device__ int2 g_edges[EMAX / 2 + 128];
__device__ int g_ecount;                 // zero-init; reset by final block each launch
__device__ double g_acc[NB];             // zero-init; reset by final block each launch
__device__ volatile unsigned g_bar_gen;  // generation barrier: no per-launch reset
__device__ unsigned g_bar_cnt;
__device__ unsigned g_done;              // last-block-done counter; reset each launch

__device__ __forceinline__ void grid_barrier() {
    __syncthreads();
    if (threadIdx.x == 0) {
        unsigned gen = g_bar_gen;
        __threadfence();
        if (atomicAdd(&g_bar_cnt, 1u) == NBLK - 1) {
            g_bar_cnt = 0;
            __threadfence();
            g_bar_gen = gen + 1;
        } else {
            while (g_bar_gen == gen) __nanosleep(32);
            __threadfence();
        }
    }
    __syncthreads();
}

__global__ void __launch_bounds__(256, 4)
fused_kernel(const float* __restrict__ dx, const float* __restrict__ x,
             const int* __restrict__ es, const int* __restrict__ ed,
             float* __restrict__ out, int E) {
    // float4-tiled staging (float view for the conversion pass)
    __shared__ float4 sx4[NB][TILE_V * 3 / 4 + 1];   // [8][97]
    __shared__ float4 sdx4[NB][TILE_V * 3 / 4 + 1];
    __shared__ int wsum[8];
    __shared__ int sbase;
    __shared__ float sacc[8][9];
    __shared__ bool slast;

    const int tid  = threadIdx.x;
    const int bid  = blockIdx.x;
    const int lane = tid & 31;
    const int warp = tid >> 5;

    if (bid < TBLK) {
        // --------------- phase 1a: transpose to fp16 records ---------------
        for (int t = bid; t < NTILES; t += TBLK) {
            const int v0 = t * TILE_V;
            const int nv = min(TILE_V, NV - v0);
            const int nf4 = nv * 3 / 4;               // float4s per batch row
            // Read: 8 batch rows x 96 float4s = 768 float4 loads, coalesced.
            #pragma unroll
            for (int k = 0; k < 3; k++) {
                int i = k * 256 + tid;                // [0, 768)
                int b = i / 96;
                int j = i - b * 96;
                size_t g4 = (size_t)b * (NV * 3 / 4) + (size_t)v0 * 3 / 4 + j;
                if (j < nf4) {
                    sx4[b][j]  = ((const float4*)x)[g4];
                    sdx4[b][j] = ((const float4*)dx)[g4];
                }
            }
            __syncthreads();
            const float* sxf  = (const float*)sx4;
            const float* sdxf = (const float*)sdx4;
            const int ROWF = (TILE_V * 3 / 4 + 1) * 4;     // floats per smem row
            uint4* outp = g_v + (size_t)v0 * NB;
            #pragma unroll
            for (int k = 0; k < 4; k++) {
                int rec = k * 256 + tid;              // [0, 1024)
                int v = rec >> 3;
                int b = rec & (NB - 1);
                if (v < nv) {
                    int j = b * ROWF + v * 3;
                    __half2 h0 = __floats2half2_rn(sxf[j],      sxf[j + 1]);
                    __half2 h1 = __floats2half2_rn(sxf[j + 2],  sdxf[j]);
                    __half2 h2 = __floats2half2_rn(sdxf[j + 1], sdxf[j + 2]);
                    uint4 r;
                    r.x = *(unsigned int*)&h0;
                    r.y = *(unsigned int*)&h1;
                    r.z = *(unsigned int*)&h2;
                    r.w = 0u;
                    outp[rec] = r;
                }
            }
            __syncthreads();
        }
    } else {
        // --------------- phase 1b: compact s<d edges (overlapped) ---------------
        const int cid = bid - TBLK;
        const int nchunks = (E + CHUNK - 1) / CHUNK;
        for (int c = cid; c < nchunks; c += CBLK) {
            const int base = c * CHUNK;
            int s[8], d[8];
            bool f[8];
            int cnt = 0;
            #pragma unroll
            for (int k = 0; k < 8; k++) {
                int e = base + k * 256 + tid;
                bool fl = false; int ss = 0, dd = 0;
                if (e < E) { ss = es[e]; dd = ed[e]; fl = ss < dd; }
                s[k] = ss; d[k] = dd; f[k] = fl; cnt += fl;
            }
            int inc = cnt;
            #pragma unroll
            for (int o = 1; o < 32; o <<= 1) {
                int t2 = __shfl_up_sync(0xffffffffu, inc, o);
                if (lane >= o) inc += t2;
            }
            if (lane == 31) wsum[warp] = inc;
            __syncthreads();
            if (tid == 0) {
                int tot = 0;
                #pragma unroll
                for (int w = 0; w < 8; w++) { int t2 = wsum[w]; wsum[w] = tot; tot += t2; }
                sbase = atomicAdd(&g_ecount, tot);
            }
            __syncthreads();
            int pos = sbase + wsum[warp] + (inc - cnt);
            #pragma unroll
            for (int k = 0; k < 8; k++)
                if (f[k]) g_edges[pos++] = make_int2(s[k], d[k]);
            __syncthreads();
        }
    }

    grid_barrier();

    // ------------------- phase 2: edge gather + reduce (ILP x2) -------------------
    const int EC  = *(volatile int*)&g_ecount;
    const int b   = lane & 7;
    const int grp = lane >> 3;
    const int gwarp = bid * 8 + warp;
    const int stride = NBLK * 8 * 4;

    float acc = 0.f;
    int e = gwarp * 4 + grp;
    for (; e + stride < EC; e += 2 * stride) {
        int2 sd0 = g_edges[e];
        int2 sd1 = g_edges[e + stride];
        uint4 rs0 = g_v[(unsigned)sd0.x * NB + b];
        uint4 rd0 = g_v[(unsigned)sd0.y * NB + b];
        uint4 rs1 = g_v[(unsigned)sd1.x * NB + b];
        uint4 rd1 = g_v[(unsigned)sd1.y * NB + b];
        {
            __half2 e0 = __hsub2(*(__half2*)&rd0.x, *(__half2*)&rs0.x);
            __half2 e1 = __hsub2(*(__half2*)&rd0.y, *(__half2*)&rs0.y);
            __half2 e2 = __hsub2(*(__half2*)&rd0.z, *(__half2*)&rs0.z);
            float2 f0 = __half22float2(e0);
            float2 f1 = __half22float2(e1);
            float2 f2 = __half22float2(e2);
            float diffx = f0.x * f0.x + f0.y * f0.y + f1.x * f1.x;
            float diffd = f1.y * f1.y + f2.x * f2.x + f2.y * f2.y;
            acc += fabsf(diffx - diffd);
        }
        {
            __half2 e0 = __hsub2(*(__half2*)&rd1.x, *(__half2*)&rs1.x);
            __half2 e1 = __hsub2(*(__half2*)&rd1.y, *(__half2*)&rs1.y);
            __half2 e2 = __hsub2(*(__half2*)&rd1.z, *(__half2*)&rs1.z);
            float2 f0 = __half22float2(e0);
            float2 f1 = __half22float2(e1);
            float2 f2 = __half22float2(e2);
            float diffx = f0.x * f0.x + f0.y * f0.y + f1.x * f1.x;
            float diffd = f1.y * f1.y + f2.x * f2.x + f2.y * f2.y;
            acc += fabsf(diffx - diffd);
        }
    }
    for (; e < EC; e += stride) {
        int2 sd = g_edges[e];
        uint4 rs = g_v[(unsigned)sd.x * NB + b];
        uint4 rd = g_v[(unsigned)sd.y * NB + b];
        __half2 e0 = __hsub2(*(__half2*)&rd.x, *(__half2*)&rs.x);
        __half2 e1 = __hsub2(*(__half2*)&rd.y, *(__half2*)&rs.y);
        __half2 e2 = __hsub2(*(__half2*)&rd.z, *(__half2*)&rs.z);
        float2 f0 = __half22float2(e0);
        float2 f1 = __half22float2(e1);
        float2 f2 = __half22float2(e2);
        float diffx = f0.x * f0.x + f0.y * f0.y + f1.x * f1.x;
        float diffd = f1.y * f1.y + f2.x * f2.x + f2.y * f2.y;
        acc += fabsf(diffx - diffd);
    }

    acc += __shfl_xor_sync(0xffffffff, acc, 8);
    acc += __shfl_xor_sync(0xffffffff, acc, 16);

    if (lane < 8) sacc[warp][b] = acc;
    __syncthreads();
    if (warp == 0 && lane < 8) {
        float s = 0.f;
        #pragma unroll
        for (int w = 0; w < 8; w++) s += sacc[w][lane];
        atomicAdd(&g_acc[lane], (double)s);
    }
    __syncthreads();

    // ------------- last-block finalize (no second grid barrier) -------------
    if (tid == 0) {
        __threadfence();
        slast = (atomicAdd(&g_done, 1u) == NBLK - 1);
    }
    __syncthreads();
    if (slast) {
        if (tid < NB) {
            double a = *(volatile double*)&g_acc[tid];
            out[tid] = (float)(2.0 * a / (double)E);
            g_acc[tid] = 0.0;
        }
        if (tid == NB) g_ecount = 0;
        if (tid == NB + 1) g_done = 0;
    }
}

extern "C" void kernel_launch(void* const* d_in, const int* in_sizes, int n_in,
                              void* d_out, int out_size) {
    // metadata order: dx, x, edge_src, edge_dst
    const float* dx = (const float*)d_in[0];
    const float* x  = (const float*)d_in[1];
    const int* es   = (const int*)d_in[2];
    const int* ed   = (const int*)d_in[3];
    float* out      = (float*)d_out;
    const int E     = in_sizes[2];

    fused_kernel<<<NBLK, 256>>>(dx, x, es, ed, out, E);
}

// round 6
// speedup vs baseline: 1.3253x; 1.0084x over previous
#include <cuda_runtime.h>
#include <cuda_fp16.h>
#include <math.h>

// Problem constants (fixed by the reference)
#define NV 100000
#define NB 8
#define TILE_V 128
#define NTILES ((NV + TILE_V - 1) / TILE_V)   // 782
#define NBLK 592                               // 148 SMs x 4 blocks
#define TBLK 400                               // transpose blocks in kernel A
#define CBLK (NBLK - TBLK)                     // compact blocks in kernel A
#define CHUNK 2048
#define EMAX 1200064
#define NWARPS (NBLK * 8)

// Scratch: 16B fp16 record per (v,b): half2{x0,x1}, half2{x2,dx0}, half2{dx1,dx2}, pad.
// One vertex = 8 records = 128B line. Total 12.8 MB.
__device__ uint4 g_v[(size_t)NV * NB];
__device__ int2 g_edges[EMAX / 2 + 128];
__device__ int g_ecount;                 // zero-init; reset by kernel B's final block
__device__ double g_acc[NB];             // zero-init; reset by kernel B's final block
__device__ unsigned g_done;              // zero-init; reset by kernel B's final block

// ---------------------------------------------------------------------------
// Kernel A: transpose (blocks [0,TBLK)) overlapped with edge compaction
// (blocks [TBLK,NBLK)). Kernel boundary acts as the grid barrier.
// ---------------------------------------------------------------------------
__global__ void __launch_bounds__(256, 4)
prep_kernel(const float* __restrict__ dx, const float* __restrict__ x,
            const int* __restrict__ es, const int* __restrict__ ed, int E) {
    __shared__ float4 sx4[NB][TILE_V * 3 / 4 + 1];   // [8][97]
    __shared__ float4 sdx4[NB][TILE_V * 3 / 4 + 1];
    __shared__ int wsum[8];
    __shared__ int sbase;

    const int tid  = threadIdx.x;
    const int bid  = blockIdx.x;
    const int lane = tid & 31;
    const int warp = tid >> 5;

    if (bid < TBLK) {
        for (int t = bid; t < NTILES; t += TBLK) {
            const int v0 = t * TILE_V;
            const int nv = min(TILE_V, NV - v0);
            const int nf4 = nv * 3 / 4;
            #pragma unroll
            for (int k = 0; k < 3; k++) {
                int i = k * 256 + tid;                // [0, 768)
                int b = i / 96;
                int j = i - b * 96;
                size_t g4 = (size_t)b * (NV * 3 / 4) + (size_t)v0 * 3 / 4 + j;
                if (j < nf4) {
                    sx4[b][j]  = ((const float4*)x)[g4];
                    sdx4[b][j] = ((const float4*)dx)[g4];
                }
            }
            __syncthreads();
            const float* sxf  = (const float*)sx4;
            const float* sdxf = (const float*)sdx4;
            const int ROWF = (TILE_V * 3 / 4 + 1) * 4;
            uint4* outp = g_v + (size_t)v0 * NB;
            #pragma unroll
            for (int k = 0; k < 4; k++) {
                int rec = k * 256 + tid;              // [0, 1024)
                int v = rec >> 3;
                int b = rec & (NB - 1);
                if (v < nv) {
                    int j = b * ROWF + v * 3;
                    __half2 h0 = __floats2half2_rn(sxf[j],      sxf[j + 1]);
                    __half2 h1 = __floats2half2_rn(sxf[j + 2],  sdxf[j]);
                    __half2 h2 = __floats2half2_rn(sdxf[j + 1], sdxf[j + 2]);
                    uint4 r;
                    r.x = *(unsigned int*)&h0;
                    r.y = *(unsigned int*)&h1;
                    r.z = *(unsigned int*)&h2;
                    r.w = 0u;
                    outp[rec] = r;
                }
            }
            __syncthreads();
        }
    } else {
        const int cid = bid - TBLK;
        const int nchunks = (E + CHUNK - 1) / CHUNK;
        for (int c = cid; c < nchunks; c += CBLK) {
            const int base = c * CHUNK;
            int s[8], d[8];
            bool f[8];
            int cnt = 0;
            #pragma unroll
            for (int k = 0; k < 8; k++) {
                int e = base + k * 256 + tid;
                bool fl = false; int ss = 0, dd = 0;
                if (e < E) { ss = es[e]; dd = ed[e]; fl = ss < dd; }
                s[k] = ss; d[k] = dd; f[k] = fl; cnt += fl;
            }
            int inc = cnt;
            #pragma unroll
            for (int o = 1; o < 32; o <<= 1) {
                int t2 = __shfl_up_sync(0xffffffffu, inc, o);
                if (lane >= o) inc += t2;
            }
            if (lane == 31) wsum[warp] = inc;
            __syncthreads();
            if (tid == 0) {
                int tot = 0;
                #pragma unroll
                for (int w = 0; w < 8; w++) { int t2 = wsum[w]; wsum[w] = tot; tot += t2; }
                sbase = atomicAdd(&g_ecount, tot);
            }
            __syncthreads();
            int pos = sbase + wsum[warp] + (inc - cnt);
            #pragma unroll
            for (int k = 0; k < 8; k++)
                if (f[k]) g_edges[pos++] = make_int2(s[k], d[k]);
            __syncthreads();
        }
    }
}

// ---------------------------------------------------------------------------
// Kernel B: edge gather + reduce + finalize.
// Contiguous per-warp edge ranges (src locality -> L1 hits) with a 4-deep
// unrolled body: 4 independent edge loads + 8 independent gathers in flight.
// ---------------------------------------------------------------------------
__device__ __forceinline__ float edge_term(uint4 rs, uint4 rd) {
    __half2 e0 = __hsub2(*(__half2*)&rd.x, *(__half2*)&rs.x);
    __half2 e1 = __hsub2(*(__half2*)&rd.y, *(__half2*)&rs.y);
    __half2 e2 = __hsub2(*(__half2*)&rd.z, *(__half2*)&rs.z);
    float2 f0 = __half22float2(e0);
    float2 f1 = __half22float2(e1);
    float2 f2 = __half22float2(e2);
    float diffx = f0.x * f0.x + f0.y * f0.y + f1.x * f1.x;
    float diffd = f1.y * f1.y + f2.x * f2.x + f2.y * f2.y;
    return fabsf(diffx - diffd);
}

__global__ void __launch_bounds__(256, 4)
edge_kernel(float* __restrict__ out, int E) {
    __shared__ float sacc[8][9];
    __shared__ bool slast;

    const int tid  = threadIdx.x;
    const int lane = tid & 31;
    const int warp = tid >> 5;
    const int b    = lane & 7;
    const int grp  = lane >> 3;
    const int gwarp = blockIdx.x * 8 + warp;

    const int EC  = *(volatile int*)&g_ecount;
    const int per = (EC + NWARPS - 1) / NWARPS;    // ~127 contiguous edges per warp
    const int start = gwarp * per;
    const int end   = min(start + per, EC);

    float acc = 0.f;
    int e = start + grp;
    // steady state: 16 edges per warp-iteration, 4 per lane-group, all loads independent
    for (; e + 12 < end; e += 16) {
        int2 sd0 = g_edges[e];
        int2 sd1 = g_edges[e + 4];
        int2 sd2 = g_edges[e + 8];
        int2 sd3 = g_edges[e + 12];
        uint4 a0 = g_v[(unsigned)sd0.x * NB + b];
        uint4 c0 = g_v[(unsigned)sd0.y * NB + b];
        uint4 a1 = g_v[(unsigned)sd1.x * NB + b];
        uint4 c1 = g_v[(unsigned)sd1.y * NB + b];
        uint4 a2 = g_v[(unsigned)sd2.x * NB + b];
        uint4 c2 = g_v[(unsigned)sd2.y * NB + b];
        uint4 a3 = g_v[(unsigned)sd3.x * NB + b];
        uint4 c3 = g_v[(unsigned)sd3.y * NB + b];
        acc += edge_term(a0, c0);
        acc += edge_term(a1, c1);
        acc += edge_term(a2, c2);
        acc += edge_term(a3, c3);
    }
    for (; e < end; e += 4) {
        int2 sd = g_edges[e];
        uint4 rs = g_v[(unsigned)sd.x * NB + b];
        uint4 rd = g_v[(unsigned)sd.y * NB + b];
        acc += edge_term(rs, rd);
    }

    acc += __shfl_xor_sync(0xffffffff, acc, 8);
    acc += __shfl_xor_sync(0xffffffff, acc, 16);

    if (lane < 8) sacc[warp][b] = acc;
    __syncthreads();
    if (warp == 0 && lane < 8) {
        float s = 0.f;
        #pragma unroll
        for (int w = 0; w < 8; w++) s += sacc[w][lane];
        atomicAdd(&g_acc[lane], (double)s);
    }
    __syncthreads();

    // last-block finalize + state reset (keeps launches deterministic)
    if (tid == 0) {
        __threadfence();
        slast = (atomicAdd(&g_done, 1u) == NBLK - 1);
    }
    __syncthreads();
    if (slast) {
        if (tid < NB) {
            double a = *(volatile double*)&g_acc[tid];
            out[tid] = (float)(2.0 * a / (double)E);
            g_acc[tid] = 0.0;
        }
        if (tid == NB) g_ecount = 0;
        if (tid == NB + 1) g_done = 0;
    }
}

extern "C" void kernel_launch(void* const* d_in, const int* in_sizes, int n_in,
                              void* d_out, int out_size) {
    // metadata order: dx, x, edge_src, edge_dst
    const float* dx = (const float*)d_in[0];
    const float* x  = (const float*)d_in[1];
    const int* es   = (const int*)d_in[2];
    const int* ed   = (const int*)d_in[3];
    float* out      = (float*)d_out;
    const int E     = in_sizes[2];

    prep_kernel<<<NBLK, 256>>>(dx, x, es, ed, E);
    edge_kernel<<<NBLK, 256>>>(out, E);
}